// round 1
// baseline (speedup 1.0000x reference)
#include <cuda_runtime.h>
#include <math.h>

// Problem constants
#define BSZ 2
#define LSEQ 2048
#define HID 2048
#define NH 16
#define HD 128
#define MTOT (BSZ * LSEQ)          // 4096
#define SCALE 0.08838834764831845f // 1/sqrt(128)

// ---------------- scratch (no allocations allowed) ----------------
__device__ float g_Q[MTOT * HID];  // 32 MB
__device__ float g_K[MTOT * HD];   // 2 MB
__device__ float g_V[MTOT * HD];   // 2 MB
__device__ float g_O[MTOT * HID];  // 32 MB

// ---------------- GEMM: C[M,N] = A[M,K] @ W[N,K]^T ----------------
// Classic 128x128x16 tiling, 256 threads, 8x8 register tile / thread.
#define GBM 128
#define GBN 128
#define GBK 16

__global__ __launch_bounds__(256) void gemm_nt(
    const float* __restrict__ A, const float* __restrict__ W,
    float* __restrict__ C, int M, int N, int K)
{
    __shared__ float As[GBK][GBM];
    __shared__ float Ws[GBK][GBN];

    const int bm = blockIdx.y * GBM;
    const int bn = blockIdx.x * GBN;
    const int tid = threadIdx.x;
    const int tx = tid & 15;   // 16 thread-cols
    const int ty = tid >> 4;   // 16 thread-rows

    float acc[8][8];
#pragma unroll
    for (int i = 0; i < 8; i++)
#pragma unroll
        for (int j = 0; j < 8; j++) acc[i][j] = 0.f;

    for (int k0 = 0; k0 < K; k0 += GBK) {
        // Load A tile (128x16) transposed into As[k][m]
#pragma unroll
        for (int jj = 0; jj < 2; jj++) {
            int f = tid + jj * 256;          // 0..511 float4 index
            int row = f >> 2;                // 0..127
            int c4 = (f & 3) * 4;            // 0,4,8,12
            float4 v = *(const float4*)(A + (size_t)(bm + row) * K + k0 + c4);
            As[c4 + 0][row] = v.x;
            As[c4 + 1][row] = v.y;
            As[c4 + 2][row] = v.z;
            As[c4 + 3][row] = v.w;
        }
        // Load W tile (128x16) transposed into Ws[k][n]
#pragma unroll
        for (int jj = 0; jj < 2; jj++) {
            int f = tid + jj * 256;
            int row = f >> 2;
            int c4 = (f & 3) * 4;
            float4 v = *(const float4*)(W + (size_t)(bn + row) * K + k0 + c4);
            Ws[c4 + 0][row] = v.x;
            Ws[c4 + 1][row] = v.y;
            Ws[c4 + 2][row] = v.z;
            Ws[c4 + 3][row] = v.w;
        }
        __syncthreads();

#pragma unroll
        for (int kk = 0; kk < GBK; kk++) {
            float a[8], b[8];
            float4 a0 = *(const float4*)&As[kk][ty * 8];
            float4 a1 = *(const float4*)&As[kk][ty * 8 + 4];
            float4 b0 = *(const float4*)&Ws[kk][tx * 8];
            float4 b1 = *(const float4*)&Ws[kk][tx * 8 + 4];
            a[0] = a0.x; a[1] = a0.y; a[2] = a0.z; a[3] = a0.w;
            a[4] = a1.x; a[5] = a1.y; a[6] = a1.z; a[7] = a1.w;
            b[0] = b0.x; b[1] = b0.y; b[2] = b0.z; b[3] = b0.w;
            b[4] = b1.x; b[5] = b1.y; b[6] = b1.z; b[7] = b1.w;
#pragma unroll
            for (int i = 0; i < 8; i++)
#pragma unroll
                for (int j = 0; j < 8; j++)
                    acc[i][j] = fmaf(a[i], b[j], acc[i][j]);
        }
        __syncthreads();
    }

    // Write back
#pragma unroll
    for (int i = 0; i < 8; i++) {
        float* crow = C + (size_t)(bm + ty * 8 + i) * N + bn + tx * 8;
        float4 v0 = make_float4(acc[i][0], acc[i][1], acc[i][2], acc[i][3]);
        float4 v1 = make_float4(acc[i][4], acc[i][5], acc[i][6], acc[i][7]);
        *(float4*)(crow) = v0;
        *(float4*)(crow + 4) = v1;
    }
}

// ---------------- Flash attention (fp32, causal, MQA) ----------------
// grid: (LSEQ/64, BSZ*NH). 256 threads. Online softmax.
#define FBM 64
#define FBN 64
#define FPAD 4
#define FSTR (HD + FPAD)  // 132 floats per row (bank-conflict pad)

// dyn smem: Q(64*132) + K(64*132) + V(64*132) + S(64*64) + m/l/corr(3*64)
#define FLASH_SMEM ((3 * FBM * FSTR + FBM * FBN + 3 * FBM) * (int)sizeof(float))

__global__ __launch_bounds__(256) void flash_kernel(
    const float* __restrict__ Q, const float* __restrict__ K,
    const float* __restrict__ V, const int* __restrict__ mask,
    float* __restrict__ O)
{
    extern __shared__ float fsm[];
    float* Qs = fsm;
    float* Ks = Qs + FBM * FSTR;
    float* Vs = Ks + FBN * FSTR;
    float* Ss = Vs + FBN * FSTR;
    float* m_sh = Ss + FBM * FBN;
    float* l_sh = m_sh + FBM;
    float* c_sh = l_sh + FBM;

    const int m0 = blockIdx.x * FBM;
    const int bh = blockIdx.y;
    const int b = bh / NH;
    const int h = bh % NH;
    const int tid = threadIdx.x;
    const int tx = tid & 15;   // 16 cols of threads
    const int ty = tid >> 4;   // 16 rows of threads

    // Load Q tile: rows m0..m0+63 of head h.  64*128 floats = 2048 float4
    for (int f = tid; f < FBM * (HD / 4); f += 256) {
        int row = f / (HD / 4);
        int c4 = (f % (HD / 4)) * 4;
        float4 v = *(const float4*)(Q + (size_t)(b * LSEQ + m0 + row) * HID + h * HD + c4);
        *(float4*)&Qs[row * FSTR + c4] = v;
    }
    if (tid < FBM) { m_sh[tid] = -1e30f; l_sh[tid] = 0.f; }

    float o[4][8];
#pragma unroll
    for (int i = 0; i < 4; i++)
#pragma unroll
        for (int j = 0; j < 8; j++) o[i][j] = 0.f;

    __syncthreads();

    const int ntiles = m0 / FBN + 1;  // causal early exit
    for (int t = 0; t < ntiles; t++) {
        const int n0 = t * FBN;
        // Load K,V tiles
        for (int f = tid; f < FBN * (HD / 4); f += 256) {
            int row = f / (HD / 4);
            int c4 = (f % (HD / 4)) * 4;
            size_t gidx = (size_t)(b * LSEQ + n0 + row) * HD + c4;
            *(float4*)&Ks[row * FSTR + c4] = *(const float4*)(K + gidx);
            *(float4*)&Vs[row * FSTR + c4] = *(const float4*)(V + gidx);
        }
        __syncthreads();

        // S = Q @ K^T  (each thread 4x4)
        float s[4][4];
#pragma unroll
        for (int i = 0; i < 4; i++)
#pragma unroll
            for (int j = 0; j < 4; j++) s[i][j] = 0.f;

        for (int d = 0; d < HD; d += 4) {
            float4 qv[4], kv[4];
#pragma unroll
            for (int i = 0; i < 4; i++)
                qv[i] = *(const float4*)&Qs[(ty * 4 + i) * FSTR + d];
#pragma unroll
            for (int j = 0; j < 4; j++)
                kv[j] = *(const float4*)&Ks[(tx * 4 + j) * FSTR + d];
#pragma unroll
            for (int i = 0; i < 4; i++)
#pragma unroll
                for (int j = 0; j < 4; j++) {
                    s[i][j] = fmaf(qv[i].x, kv[j].x, s[i][j]);
                    s[i][j] = fmaf(qv[i].y, kv[j].y, s[i][j]);
                    s[i][j] = fmaf(qv[i].z, kv[j].z, s[i][j]);
                    s[i][j] = fmaf(qv[i].w, kv[j].w, s[i][j]);
                }
        }

        // Scale + causal + pad mask, store to Ss
#pragma unroll
        for (int i = 0; i < 4; i++) {
            int qidx = m0 + ty * 4 + i;
#pragma unroll
            for (int j = 0; j < 4; j++) {
                int kidx = n0 + tx * 4 + j;
                float val = s[i][j] * SCALE;
                if (kidx > qidx || mask[b * LSEQ + kidx] == 0) val = -1e30f;
                Ss[(ty * 4 + i) * FBN + tx * 4 + j] = val;
            }
        }
        __syncthreads();

        // Online softmax: 4 threads per row, 16 cols each
        {
            const int row = tid >> 2;
            const int quad = tid & 3;
            const int cbase = quad * 16;
            float mx = -1e30f;
#pragma unroll
            for (int c = 0; c < 16; c++)
                mx = fmaxf(mx, Ss[row * FBN + cbase + c]);
            mx = fmaxf(mx, __shfl_xor_sync(0xffffffffu, mx, 1));
            mx = fmaxf(mx, __shfl_xor_sync(0xffffffffu, mx, 2));
            float mo = m_sh[row];
            float mn = fmaxf(mo, mx);
            float sum = 0.f;
#pragma unroll
            for (int c = 0; c < 16; c++) {
                float p = __expf(Ss[row * FBN + cbase + c] - mn);
                Ss[row * FBN + cbase + c] = p;
                sum += p;
            }
            sum += __shfl_xor_sync(0xffffffffu, sum, 1);
            sum += __shfl_xor_sync(0xffffffffu, sum, 2);
            if (quad == 0) {
                float cr = __expf(mo - mn);
                c_sh[row] = cr;
                l_sh[row] = l_sh[row] * cr + sum;
                m_sh[row] = mn;
            }
        }
        __syncthreads();

        // Rescale O accumulator, then O += P @ V
#pragma unroll
        for (int i = 0; i < 4; i++) {
            float cr = c_sh[ty * 4 + i];
#pragma unroll
            for (int j = 0; j < 8; j++) o[i][j] *= cr;
        }
        for (int n = 0; n < FBN; n++) {
            float4 v0 = *(const float4*)&Vs[n * FSTR + tx * 8];
            float4 v1 = *(const float4*)&Vs[n * FSTR + tx * 8 + 4];
            float vv[8] = {v0.x, v0.y, v0.z, v0.w, v1.x, v1.y, v1.z, v1.w};
#pragma unroll
            for (int i = 0; i < 4; i++) {
                float p = Ss[(ty * 4 + i) * FBN + n];
#pragma unroll
                for (int j = 0; j < 8; j++)
                    o[i][j] = fmaf(p, vv[j], o[i][j]);
            }
        }
        __syncthreads();
    }

    // Finalize: divide by l, write out [b, q, h*HD + c]
#pragma unroll
    for (int i = 0; i < 4; i++) {
        int row = ty * 4 + i;
        float l = l_sh[row];
        float inv = (l > 0.f) ? (1.f / l) : 0.f;
        float* orow = O + (size_t)(b * LSEQ + m0 + row) * HID + h * HD + tx * 8;
        float4 v0 = make_float4(o[i][0] * inv, o[i][1] * inv, o[i][2] * inv, o[i][3] * inv);
        float4 v1 = make_float4(o[i][4] * inv, o[i][5] * inv, o[i][6] * inv, o[i][7] * inv);
        *(float4*)(orow) = v0;
        *(float4*)(orow + 4) = v1;
    }
}

// ---------------- launch ----------------
extern "C" void kernel_launch(void* const* d_in, const int* in_sizes, int n_in,
                              void* d_out, int out_size)
{
    const float* x   = (const float*)d_in[0];
    const int* mask  = (const int*)d_in[1];
    const float* Wq  = (const float*)d_in[2];
    const float* Wk  = (const float*)d_in[3];
    const float* Wv  = (const float*)d_in[4];
    const float* Wo  = (const float*)d_in[5];
    float* out       = (float*)d_out;

    float *Qp, *Kp, *Vp, *Op;
    cudaGetSymbolAddress((void**)&Qp, g_Q);
    cudaGetSymbolAddress((void**)&Kp, g_K);
    cudaGetSymbolAddress((void**)&Vp, g_V);
    cudaGetSymbolAddress((void**)&Op, g_O);

    cudaFuncSetAttribute(flash_kernel, cudaFuncAttributeMaxDynamicSharedMemorySize,
                         FLASH_SMEM);

    // Q projection: [4096,2048] = x @ Wq^T
    gemm_nt<<<dim3(HID / GBN, MTOT / GBM), 256>>>(x, Wq, Qp, MTOT, HID, HID);
    // K,V projections: [4096,128]
    gemm_nt<<<dim3(HD / GBN, MTOT / GBM), 256>>>(x, Wk, Kp, MTOT, HD, HID);
    gemm_nt<<<dim3(HD / GBN, MTOT / GBM), 256>>>(x, Wv, Vp, MTOT, HD, HID);
    // Attention
    flash_kernel<<<dim3(LSEQ / FBM, BSZ * NH), 256, FLASH_SMEM>>>(Qp, Kp, Vp, mask, Op);
    // Output projection
    gemm_nt<<<dim3(HID / GBN, MTOT / GBM), 256>>>(Op, Wo, out, MTOT, HID, HID);
}

// round 5
// speedup vs baseline: 1.5425x; 1.5425x over previous
#include <cuda_runtime.h>
#include <cstdint>
#include <math.h>

// Problem constants
#define BSZ 2
#define LSEQ 2048
#define HID 2048
#define NH 16
#define HD 128
#define MTOT (BSZ * LSEQ)          // 4096
#define SCALE 0.08838834764831845f // 1/sqrt(128)

// ---------------- scratch (no allocations allowed) ----------------
__device__ float g_Q[MTOT * HID];  // 32 MB
__device__ float g_K[MTOT * HD];   // 2 MB
__device__ float g_V[MTOT * HD];   // 2 MB
__device__ float g_O[MTOT * HID];  // 32 MB

// cvt.rna.tf32.f32 writes a .b32 destination -> "=r" constraint.
__device__ __forceinline__ uint32_t tf32r(float x) {
    uint32_t y;
    asm("cvt.rna.tf32.f32 %0, %1;" : "=r"(y) : "f"(x));
    return y;
}

__device__ __forceinline__ void mma_tf32(float* c, const uint32_t* a,
                                         uint32_t b0, uint32_t b1) {
    asm volatile(
        "mma.sync.aligned.m16n8k8.row.col.f32.tf32.tf32.f32 "
        "{%0,%1,%2,%3}, {%4,%5,%6,%7}, {%8,%9}, {%0,%1,%2,%3};\n"
        : "+f"(c[0]), "+f"(c[1]), "+f"(c[2]), "+f"(c[3])
        : "r"(a[0]), "r"(a[1]), "r"(a[2]), "r"(a[3]), "r"(b0), "r"(b1));
}

// ================= mma.sync tf32 GEMM: C[M,N] = A[M,K] @ W[N,K]^T =================
// CTA 128x128, 256 threads (8 warps as 4x2; warp tile 32x64). K chunk 32.
#define TBM 128
#define TBN 128
#define TBK 32
#define GK 2048
#define NCHUNK (GK / TBK)   // 64
#define APAD 36             // smem row stride in words (32 data + 4 pad)
#define ATILE (TBM * APAD)  // words per A (or B) tile
#define STAGEF (2 * ATILE)  // words per stage (A + B)
#define GEMM_SMEM (2 * STAGEF * (int)sizeof(uint32_t))  // 73728 B

__global__ __launch_bounds__(256) void gemm_tc(
    const float* __restrict__ A, const float* __restrict__ W,
    float* __restrict__ C, int ldc)
{
    extern __shared__ uint32_t smw[];
    const int tid = threadIdx.x;
    const int lane = tid & 31;
    const int wid = tid >> 5;
    const int warp_m = (wid & 3) * 32;   // 4 warps along M
    const int warp_n = (wid >> 2) * 64;  // 2 warps along N
    const int gid = lane >> 2;           // 0..7
    const int tig = lane & 3;            // 0..3
    const int bm = blockIdx.y * TBM;
    const int bn = blockIdx.x * TBN;

    // per-thread global-load coords (4 float4 per tile)
    const int lrow = tid >> 3;           // 0..31 (+32*i)
    const int lc4 = (tid & 7) * 4;       // 0,4,...,28

    float acc[2][8][4];
#pragma unroll
    for (int i = 0; i < 2; i++)
#pragma unroll
        for (int j = 0; j < 8; j++)
#pragma unroll
            for (int q = 0; q < 4; q++) acc[i][j][q] = 0.f;

    float4 ra[4], rb[4];

    // ---- prefetch chunk 0 ----
#pragma unroll
    for (int i = 0; i < 4; i++) {
        int row = lrow + i * 32;
        ra[i] = *(const float4*)(A + (size_t)(bm + row) * GK + lc4);
        rb[i] = *(const float4*)(W + (size_t)(bn + row) * GK + lc4);
    }
#pragma unroll
    for (int i = 0; i < 4; i++) {
        int row = lrow + i * 32;
        uint32_t* pa = &smw[row * APAD + lc4];
        uint32_t* pb = &smw[ATILE + row * APAD + lc4];
        pa[0] = tf32r(ra[i].x); pa[1] = tf32r(ra[i].y);
        pa[2] = tf32r(ra[i].z); pa[3] = tf32r(ra[i].w);
        pb[0] = tf32r(rb[i].x); pb[1] = tf32r(rb[i].y);
        pb[2] = tf32r(rb[i].z); pb[3] = tf32r(rb[i].w);
    }
    __syncthreads();

#pragma unroll 1
    for (int c = 0; c < NCHUNK; c++) {
        const int s = c & 1;
        const bool more = (c + 1 < NCHUNK);
        // issue global loads for next chunk (latency hidden by compute)
        if (more) {
            const int k0 = (c + 1) * TBK;
#pragma unroll
            for (int i = 0; i < 4; i++) {
                int row = lrow + i * 32;
                ra[i] = *(const float4*)(A + (size_t)(bm + row) * GK + k0 + lc4);
                rb[i] = *(const float4*)(W + (size_t)(bn + row) * GK + k0 + lc4);
            }
        }

        // ---- compute from stage s ----
        const uint32_t* As_ = &smw[s * STAGEF];
        const uint32_t* Ws_ = &smw[s * STAGEF + ATILE];
#pragma unroll
        for (int ks = 0; ks < 4; ks++) {
            const int k = ks * 8;
            uint32_t af[2][4];
#pragma unroll
            for (int i = 0; i < 2; i++) {
                int r0 = warp_m + i * 16 + gid;
                af[i][0] = As_[r0 * APAD + k + tig];
                af[i][1] = As_[(r0 + 8) * APAD + k + tig];
                af[i][2] = As_[r0 * APAD + k + tig + 4];
                af[i][3] = As_[(r0 + 8) * APAD + k + tig + 4];
            }
#pragma unroll
            for (int j = 0; j < 8; j++) {
                int cn = warp_n + j * 8 + gid;
                uint32_t b0 = Ws_[cn * APAD + k + tig];
                uint32_t b1 = Ws_[cn * APAD + k + tig + 4];
                mma_tf32(acc[0][j], af[0], b0, b1);
                mma_tf32(acc[1][j], af[1], b0, b1);
            }
        }

        // ---- store next chunk into other stage ----
        if (more) {
            uint32_t* Ad = &smw[(s ^ 1) * STAGEF];
            uint32_t* Bd = &smw[(s ^ 1) * STAGEF + ATILE];
#pragma unroll
            for (int i = 0; i < 4; i++) {
                int row = lrow + i * 32;
                uint32_t* pa = &Ad[row * APAD + lc4];
                uint32_t* pb = &Bd[row * APAD + lc4];
                pa[0] = tf32r(ra[i].x); pa[1] = tf32r(ra[i].y);
                pa[2] = tf32r(ra[i].z); pa[3] = tf32r(ra[i].w);
                pb[0] = tf32r(rb[i].x); pb[1] = tf32r(rb[i].y);
                pb[2] = tf32r(rb[i].z); pb[3] = tf32r(rb[i].w);
            }
        }
        __syncthreads();
    }

    // ---- epilogue ----
#pragma unroll
    for (int i = 0; i < 2; i++) {
        int r0 = bm + warp_m + i * 16 + gid;
#pragma unroll
        for (int j = 0; j < 8; j++) {
            int cn = bn + warp_n + j * 8 + 2 * tig;
            *(float2*)(C + (size_t)r0 * ldc + cn) =
                make_float2(acc[i][j][0], acc[i][j][1]);
            *(float2*)(C + (size_t)(r0 + 8) * ldc + cn) =
                make_float2(acc[i][j][2], acc[i][j][3]);
        }
    }
}

// ---------------- Flash attention (fp32, causal, MQA) ----------------
#define FBM 64
#define FBN 64
#define FPAD 4
#define FSTR (HD + FPAD)

#define FLASH_SMEM ((3 * FBM * FSTR + FBM * FBN + 3 * FBM) * (int)sizeof(float))

__global__ __launch_bounds__(256) void flash_kernel(
    const float* __restrict__ Q, const float* __restrict__ K,
    const float* __restrict__ V, const int* __restrict__ mask,
    float* __restrict__ O)
{
    extern __shared__ float fsm[];
    float* Qs = fsm;
    float* Ks = Qs + FBM * FSTR;
    float* Vs = Ks + FBN * FSTR;
    float* Ss = Vs + FBN * FSTR;
    float* m_sh = Ss + FBM * FBN;
    float* l_sh = m_sh + FBM;
    float* c_sh = l_sh + FBM;

    const int m0 = blockIdx.x * FBM;
    const int bh = blockIdx.y;
    const int b = bh / NH;
    const int h = bh % NH;
    const int tid = threadIdx.x;
    const int tx = tid & 15;
    const int ty = tid >> 4;

    for (int f = tid; f < FBM * (HD / 4); f += 256) {
        int row = f / (HD / 4);
        int c4 = (f % (HD / 4)) * 4;
        float4 v = *(const float4*)(Q + (size_t)(b * LSEQ + m0 + row) * HID + h * HD + c4);
        *(float4*)&Qs[row * FSTR + c4] = v;
    }
    if (tid < FBM) { m_sh[tid] = -1e30f; l_sh[tid] = 0.f; }

    float o[4][8];
#pragma unroll
    for (int i = 0; i < 4; i++)
#pragma unroll
        for (int j = 0; j < 8; j++) o[i][j] = 0.f;

    __syncthreads();

    const int ntiles = m0 / FBN + 1;
    for (int t = 0; t < ntiles; t++) {
        const int n0 = t * FBN;
        for (int f = tid; f < FBN * (HD / 4); f += 256) {
            int row = f / (HD / 4);
            int c4 = (f % (HD / 4)) * 4;
            size_t gidx = (size_t)(b * LSEQ + n0 + row) * HD + c4;
            *(float4*)&Ks[row * FSTR + c4] = *(const float4*)(K + gidx);
            *(float4*)&Vs[row * FSTR + c4] = *(const float4*)(V + gidx);
        }
        __syncthreads();

        float s[4][4];
#pragma unroll
        for (int i = 0; i < 4; i++)
#pragma unroll
            for (int j = 0; j < 4; j++) s[i][j] = 0.f;

        for (int d = 0; d < HD; d += 4) {
            float4 qv[4], kv[4];
#pragma unroll
            for (int i = 0; i < 4; i++)
                qv[i] = *(const float4*)&Qs[(ty * 4 + i) * FSTR + d];
#pragma unroll
            for (int j = 0; j < 4; j++)
                kv[j] = *(const float4*)&Ks[(tx * 4 + j) * FSTR + d];
#pragma unroll
            for (int i = 0; i < 4; i++)
#pragma unroll
                for (int j = 0; j < 4; j++) {
                    s[i][j] = fmaf(qv[i].x, kv[j].x, s[i][j]);
                    s[i][j] = fmaf(qv[i].y, kv[j].y, s[i][j]);
                    s[i][j] = fmaf(qv[i].z, kv[j].z, s[i][j]);
                    s[i][j] = fmaf(qv[i].w, kv[j].w, s[i][j]);
                }
        }

#pragma unroll
        for (int i = 0; i < 4; i++) {
            int qidx = m0 + ty * 4 + i;
#pragma unroll
            for (int j = 0; j < 4; j++) {
                int kidx = n0 + tx * 4 + j;
                float val = s[i][j] * SCALE;
                if (kidx > qidx || mask[b * LSEQ + kidx] == 0) val = -1e30f;
                Ss[(ty * 4 + i) * FBN + tx * 4 + j] = val;
            }
        }
        __syncthreads();

        {
            const int row = tid >> 2;
            const int quad = tid & 3;
            const int cbase = quad * 16;
            float mx = -1e30f;
#pragma unroll
            for (int c = 0; c < 16; c++)
                mx = fmaxf(mx, Ss[row * FBN + cbase + c]);
            mx = fmaxf(mx, __shfl_xor_sync(0xffffffffu, mx, 1));
            mx = fmaxf(mx, __shfl_xor_sync(0xffffffffu, mx, 2));
            float mo = m_sh[row];
            float mn = fmaxf(mo, mx);
            float sum = 0.f;
#pragma unroll
            for (int c = 0; c < 16; c++) {
                float p = __expf(Ss[row * FBN + cbase + c] - mn);
                Ss[row * FBN + cbase + c] = p;
                sum += p;
            }
            sum += __shfl_xor_sync(0xffffffffu, sum, 1);
            sum += __shfl_xor_sync(0xffffffffu, sum, 2);
            if (quad == 0) {
                float cr = __expf(mo - mn);
                c_sh[row] = cr;
                l_sh[row] = l_sh[row] * cr + sum;
                m_sh[row] = mn;
            }
        }
        __syncthreads();

#pragma unroll
        for (int i = 0; i < 4; i++) {
            float cr = c_sh[ty * 4 + i];
#pragma unroll
            for (int j = 0; j < 8; j++) o[i][j] *= cr;
        }
        for (int n = 0; n < FBN; n++) {
            float4 v0 = *(const float4*)&Vs[n * FSTR + tx * 8];
            float4 v1 = *(const float4*)&Vs[n * FSTR + tx * 8 + 4];
            float vv[8] = {v0.x, v0.y, v0.z, v0.w, v1.x, v1.y, v1.z, v1.w};
#pragma unroll
            for (int i = 0; i < 4; i++) {
                float p = Ss[(ty * 4 + i) * FBN + n];
#pragma unroll
                for (int j = 0; j < 8; j++)
                    o[i][j] = fmaf(p, vv[j], o[i][j]);
            }
        }
        __syncthreads();
    }

#pragma unroll
    for (int i = 0; i < 4; i++) {
        int row = ty * 4 + i;
        float l = l_sh[row];
        float inv = (l > 0.f) ? (1.f / l) : 0.f;
        float* orow = O + (size_t)(b * LSEQ + m0 + row) * HID + h * HD + tx * 8;
        float4 v0 = make_float4(o[i][0] * inv, o[i][1] * inv, o[i][2] * inv, o[i][3] * inv);
        float4 v1 = make_float4(o[i][4] * inv, o[i][5] * inv, o[i][6] * inv, o[i][7] * inv);
        *(float4*)(orow) = v0;
        *(float4*)(orow + 4) = v1;
    }
}

// ---------------- launch ----------------
extern "C" void kernel_launch(void* const* d_in, const int* in_sizes, int n_in,
                              void* d_out, int out_size)
{
    const float* x   = (const float*)d_in[0];
    const int* mask  = (const int*)d_in[1];
    const float* Wq  = (const float*)d_in[2];
    const float* Wk  = (const float*)d_in[3];
    const float* Wv  = (const float*)d_in[4];
    const float* Wo  = (const float*)d_in[5];
    float* out       = (float*)d_out;

    float *Qp, *Kp, *Vp, *Op;
    cudaGetSymbolAddress((void**)&Qp, g_Q);
    cudaGetSymbolAddress((void**)&Kp, g_K);
    cudaGetSymbolAddress((void**)&Vp, g_V);
    cudaGetSymbolAddress((void**)&Op, g_O);

    cudaFuncSetAttribute(gemm_tc, cudaFuncAttributeMaxDynamicSharedMemorySize, GEMM_SMEM);
    cudaFuncSetAttribute(flash_kernel, cudaFuncAttributeMaxDynamicSharedMemorySize, FLASH_SMEM);

    // Q projection: [4096,2048] = x @ Wq^T
    gemm_tc<<<dim3(HID / TBN, MTOT / TBM), 256, GEMM_SMEM>>>(x, Wq, Qp, HID);
    // K,V projections: [4096,128]
    gemm_tc<<<dim3(HD / TBN, MTOT / TBM), 256, GEMM_SMEM>>>(x, Wk, Kp, HD);
    gemm_tc<<<dim3(HD / TBN, MTOT / TBM), 256, GEMM_SMEM>>>(x, Wv, Vp, HD);
    // Attention (fp32 SIMT this round)
    flash_kernel<<<dim3(LSEQ / FBM, BSZ * NH), 256, FLASH_SMEM>>>(Qp, Kp, Vp, mask, Op);
    // Output projection
    gemm_tc<<<dim3(HID / TBN, MTOT / TBM), 256, GEMM_SMEM>>>(Op, Wo, out, HID);
}

// round 8
// speedup vs baseline: 3.3974x; 2.2025x over previous
#include <cuda_runtime.h>
#include <cstdint>
#include <math.h>

// Problem constants
#define BSZ 2
#define LSEQ 2048
#define HID 2048
#define NH 16
#define HD 128
#define MTOT (BSZ * LSEQ)          // 4096
#define SCALE 0.08838834764831845f // 1/sqrt(128)

// ---------------- scratch (no allocations allowed) ----------------
__device__ float g_Q[MTOT * HID];  // 32 MB
__device__ float g_K[MTOT * HD];   // 2 MB
__device__ float g_V[MTOT * HD];   // 2 MB
__device__ float g_O[MTOT * HID];  // 32 MB

// cvt.rna.tf32.f32 writes a .b32 destination -> "=r" constraint.
__device__ __forceinline__ uint32_t tf32r(float x) {
    uint32_t y;
    asm("cvt.rna.tf32.f32 %0, %1;" : "=r"(y) : "f"(x));
    return y;
}

__device__ __forceinline__ void mma_tf32(float* c, const uint32_t* a,
                                         uint32_t b0, uint32_t b1) {
    asm volatile(
        "mma.sync.aligned.m16n8k8.row.col.f32.tf32.tf32.f32 "
        "{%0,%1,%2,%3}, {%4,%5,%6,%7}, {%8,%9}, {%0,%1,%2,%3};\n"
        : "+f"(c[0]), "+f"(c[1]), "+f"(c[2]), "+f"(c[3])
        : "r"(a[0]), "r"(a[1]), "r"(a[2]), "r"(a[3]), "r"(b0), "r"(b1));
}

// ================= mma.sync tf32 GEMM: C[M,N] = A[M,K] @ W[N,K]^T =================
#define TBM 128
#define TBN 128
#define TBK 32
#define GK 2048
#define NCHUNK (GK / TBK)   // 64
#define APAD 36
#define ATILE (TBM * APAD)
#define STAGEF (2 * ATILE)
#define GEMM_SMEM (2 * STAGEF * (int)sizeof(uint32_t))  // 73728 B

__global__ __launch_bounds__(256) void gemm_tc(
    const float* __restrict__ A, const float* __restrict__ W,
    float* __restrict__ C, int ldc)
{
    extern __shared__ uint32_t smw[];
    const int tid = threadIdx.x;
    const int lane = tid & 31;
    const int wid = tid >> 5;
    const int warp_m = (wid & 3) * 32;
    const int warp_n = (wid >> 2) * 64;
    const int gid = lane >> 2;
    const int tig = lane & 3;
    const int bm = blockIdx.y * TBM;
    const int bn = blockIdx.x * TBN;

    const int lrow = tid >> 3;
    const int lc4 = (tid & 7) * 4;

    float acc[2][8][4];
#pragma unroll
    for (int i = 0; i < 2; i++)
#pragma unroll
        for (int j = 0; j < 8; j++)
#pragma unroll
            for (int q = 0; q < 4; q++) acc[i][j][q] = 0.f;

    float4 ra[4], rb[4];

#pragma unroll
    for (int i = 0; i < 4; i++) {
        int row = lrow + i * 32;
        ra[i] = *(const float4*)(A + (size_t)(bm + row) * GK + lc4);
        rb[i] = *(const float4*)(W + (size_t)(bn + row) * GK + lc4);
    }
#pragma unroll
    for (int i = 0; i < 4; i++) {
        int row = lrow + i * 32;
        uint32_t* pa = &smw[row * APAD + lc4];
        uint32_t* pb = &smw[ATILE + row * APAD + lc4];
        pa[0] = tf32r(ra[i].x); pa[1] = tf32r(ra[i].y);
        pa[2] = tf32r(ra[i].z); pa[3] = tf32r(ra[i].w);
        pb[0] = tf32r(rb[i].x); pb[1] = tf32r(rb[i].y);
        pb[2] = tf32r(rb[i].z); pb[3] = tf32r(rb[i].w);
    }
    __syncthreads();

#pragma unroll 1
    for (int c = 0; c < NCHUNK; c++) {
        const int s = c & 1;
        const bool more = (c + 1 < NCHUNK);
        if (more) {
            const int k0 = (c + 1) * TBK;
#pragma unroll
            for (int i = 0; i < 4; i++) {
                int row = lrow + i * 32;
                ra[i] = *(const float4*)(A + (size_t)(bm + row) * GK + k0 + lc4);
                rb[i] = *(const float4*)(W + (size_t)(bn + row) * GK + k0 + lc4);
            }
        }

        const uint32_t* As_ = &smw[s * STAGEF];
        const uint32_t* Ws_ = &smw[s * STAGEF + ATILE];
#pragma unroll
        for (int ks = 0; ks < 4; ks++) {
            const int k = ks * 8;
            uint32_t af[2][4];
#pragma unroll
            for (int i = 0; i < 2; i++) {
                int r0 = warp_m + i * 16 + gid;
                af[i][0] = As_[r0 * APAD + k + tig];
                af[i][1] = As_[(r0 + 8) * APAD + k + tig];
                af[i][2] = As_[r0 * APAD + k + tig + 4];
                af[i][3] = As_[(r0 + 8) * APAD + k + tig + 4];
            }
#pragma unroll
            for (int j = 0; j < 8; j++) {
                int cn = warp_n + j * 8 + gid;
                uint32_t b0 = Ws_[cn * APAD + k + tig];
                uint32_t b1 = Ws_[cn * APAD + k + tig + 4];
                mma_tf32(acc[0][j], af[0], b0, b1);
                mma_tf32(acc[1][j], af[1], b0, b1);
            }
        }

        if (more) {
            uint32_t* Ad = &smw[(s ^ 1) * STAGEF];
            uint32_t* Bd = &smw[(s ^ 1) * STAGEF + ATILE];
#pragma unroll
            for (int i = 0; i < 4; i++) {
                int row = lrow + i * 32;
                uint32_t* pa = &Ad[row * APAD + lc4];
                uint32_t* pb = &Bd[row * APAD + lc4];
                pa[0] = tf32r(ra[i].x); pa[1] = tf32r(ra[i].y);
                pa[2] = tf32r(ra[i].z); pa[3] = tf32r(ra[i].w);
                pb[0] = tf32r(rb[i].x); pb[1] = tf32r(rb[i].y);
                pb[2] = tf32r(rb[i].z); pb[3] = tf32r(rb[i].w);
            }
        }
        __syncthreads();
    }

#pragma unroll
    for (int i = 0; i < 2; i++) {
        int r0 = bm + warp_m + i * 16 + gid;
#pragma unroll
        for (int j = 0; j < 8; j++) {
            int cn = bn + warp_n + j * 8 + 2 * tig;
            *(float2*)(C + (size_t)r0 * ldc + cn) =
                make_float2(acc[i][j][0], acc[i][j][1]);
            *(float2*)(C + (size_t)(r0 + 8) * ldc + cn) =
                make_float2(acc[i][j][2], acc[i][j][3]);
        }
    }
}

// ============== Tensor-core flash attention (tf32 mma, causal, MQA) ==============
// CTA: 64 q-rows x full head (d=128). 256 threads = 8 warps (4 m-rows x 2 n-cols).
// Per KV tile (64 keys): S = Q K^T via mma (warp: m16 x n32), register softmax
// with cross-warp smem exchange, P -> smem, O += P V via mma (warp: m16 x n64).
#define FBM 64
#define FBN 64
#define QSTR 132   // 128 + 4 (bank = 4*gid+tig, conflict-free)
#define VSTR 68    // 64 + 4
#define FL_QS 0
#define FL_KS (FL_QS + 64 * QSTR)
#define FL_VT (FL_KS + 64 * QSTR)
#define FL_SS (FL_VT + 128 * VSTR)
#define FL_ST (FL_SS + 64 * VSTR)            // m[64], l[64], c[64], pmx[64][2], psum[64][2]
#define FL_MK (FL_ST + 64 * 7)
#define FLASH_SMEM ((FL_MK + 64) * (int)sizeof(uint32_t))

__global__ __launch_bounds__(256) void flash_tc(
    const float* __restrict__ Q, const float* __restrict__ K,
    const float* __restrict__ V, const int* __restrict__ mask,
    float* __restrict__ O)
{
    extern __shared__ uint32_t fsw[];
    uint32_t* Qs = fsw + FL_QS;
    uint32_t* Ks = fsw + FL_KS;
    uint32_t* Vt = fsw + FL_VT;
    uint32_t* Ss = fsw + FL_SS;
    float* m_sh = (float*)(fsw + FL_ST);
    float* l_sh = m_sh + 64;
    float* c_sh = l_sh + 64;
    float* pmx  = c_sh + 64;   // [64][2]
    float* psum = pmx + 128;   // [64][2]
    int* msk_sh = (int*)(fsw + FL_MK);

    // heavy q-tiles first (better wave tail)
    const int m0 = (gridDim.x - 1 - blockIdx.x) * FBM;
    const int bh = blockIdx.y;
    const int b = bh / NH;
    const int h = bh % NH;
    const int tid = threadIdx.x;
    const int lane = tid & 31;
    const int wid = tid >> 5;
    const int gid = lane >> 2;
    const int tig = lane & 3;
    const int wm = (wid & 3) * 16;   // warp m-row
    const int wq = wid >> 2;         // warp n-col (0/1)

    // ---- load Q tile (64 x 128) as tf32 ----
    for (int f = tid; f < 64 * 32; f += 256) {
        int row = f >> 5, c4 = (f & 31) * 4;
        float4 v = *(const float4*)(Q + (size_t)(b * LSEQ + m0 + row) * HID + h * HD + c4);
        uint4 u = make_uint4(tf32r(v.x), tf32r(v.y), tf32r(v.z), tf32r(v.w));
        *(uint4*)&Qs[row * QSTR + c4] = u;
    }
    if (tid < 64) { m_sh[tid] = -1e30f; l_sh[tid] = 0.f; }

    float o[8][4];
#pragma unroll
    for (int j = 0; j < 8; j++)
#pragma unroll
        for (int c = 0; c < 4; c++) o[j][c] = 0.f;

    __syncthreads();

    const int r0 = m0 + wm + gid;
    const int r1 = r0 + 8;
    const int ntiles = m0 / FBN + 1;

#pragma unroll 1
    for (int t = 0; t < ntiles; t++) {
        const int n0 = t * FBN;
        // ---- K tile (64 x 128) ----
        for (int f = tid; f < 64 * 32; f += 256) {
            int row = f >> 5, c4 = (f & 31) * 4;
            float4 v = *(const float4*)(K + (size_t)(b * LSEQ + n0 + row) * HD + c4);
            uint4 u = make_uint4(tf32r(v.x), tf32r(v.y), tf32r(v.z), tf32r(v.w));
            *(uint4*)&Ks[row * QSTR + c4] = u;
        }
        // ---- V tile transposed: Vt[d][seq] ----
        for (int f = tid; f < 64 * 32; f += 256) {
            int row = f & 63, c4 = (f >> 6) * 4;
            float4 v = *(const float4*)(V + (size_t)(b * LSEQ + n0 + row) * HD + c4);
            Vt[(c4 + 0) * VSTR + row] = tf32r(v.x);
            Vt[(c4 + 1) * VSTR + row] = tf32r(v.y);
            Vt[(c4 + 2) * VSTR + row] = tf32r(v.z);
            Vt[(c4 + 3) * VSTR + row] = tf32r(v.w);
        }
        if (tid < 64) msk_sh[tid] = mask[b * LSEQ + n0 + tid];
        __syncthreads();

        // ---- S = Q K^T : warp computes m16 x n32 (4 n8-tiles) ----
        float s[4][4];
#pragma unroll
        for (int j = 0; j < 4; j++)
#pragma unroll
            for (int c = 0; c < 4; c++) s[j][c] = 0.f;
#pragma unroll
        for (int k = 0; k < HD; k += 8) {
            uint32_t a[4];
            a[0] = Qs[(wm + gid) * QSTR + k + tig];
            a[1] = Qs[(wm + gid + 8) * QSTR + k + tig];
            a[2] = Qs[(wm + gid) * QSTR + k + tig + 4];
            a[3] = Qs[(wm + gid + 8) * QSTR + k + tig + 4];
#pragma unroll
            for (int j = 0; j < 4; j++) {
                int n = wq * 32 + j * 8 + gid;
                uint32_t b0 = Ks[n * QSTR + k + tig];
                uint32_t b1 = Ks[n * QSTR + k + tig + 4];
                mma_tf32(s[j], a, b0, b1);
            }
        }

        // ---- scale + causal + pad mask; per-row max ----
        float mx0 = -1e30f, mx1 = -1e30f;
#pragma unroll
        for (int j = 0; j < 4; j++) {
#pragma unroll
            for (int c = 0; c < 4; c++) {
                int lcol = wq * 32 + j * 8 + 2 * tig + (c & 1);
                int col = n0 + lcol;
                int r = (c < 2) ? r0 : r1;
                float v = s[j][c] * SCALE;
                if (col > r || msk_sh[lcol] == 0) v = -1e30f;
                s[j][c] = v;
                if (c < 2) mx0 = fmaxf(mx0, v); else mx1 = fmaxf(mx1, v);
            }
        }
        mx0 = fmaxf(mx0, __shfl_xor_sync(0xffffffffu, mx0, 1));
        mx0 = fmaxf(mx0, __shfl_xor_sync(0xffffffffu, mx0, 2));
        mx1 = fmaxf(mx1, __shfl_xor_sync(0xffffffffu, mx1, 1));
        mx1 = fmaxf(mx1, __shfl_xor_sync(0xffffffffu, mx1, 2));
        if (tig == 0) {
            pmx[(wm + gid) * 2 + wq] = mx0;
            pmx[(wm + gid + 8) * 2 + wq] = mx1;
        }
        __syncthreads();

        if (tid < 64) {
            float mo = m_sh[tid];
            float mn = fmaxf(mo, fmaxf(pmx[tid * 2], pmx[tid * 2 + 1]));
            m_sh[tid] = mn;
            c_sh[tid] = __expf(mo - mn);
        }
        __syncthreads();

        // ---- exp, partial sums, write P (tf32) to Ss ----
        float mn0 = m_sh[wm + gid], mn1 = m_sh[wm + gid + 8];
        float sm0 = 0.f, sm1 = 0.f;
#pragma unroll
        for (int j = 0; j < 4; j++) {
#pragma unroll
            for (int c = 0; c < 4; c++) {
                float p = __expf(s[j][c] - ((c < 2) ? mn0 : mn1));
                s[j][c] = p;
                if (c < 2) sm0 += p; else sm1 += p;
            }
            int cb = wq * 32 + j * 8 + 2 * tig;
            Ss[(wm + gid) * VSTR + cb]     = tf32r(s[j][0]);
            Ss[(wm + gid) * VSTR + cb + 1] = tf32r(s[j][1]);
            Ss[(wm + gid + 8) * VSTR + cb]     = tf32r(s[j][2]);
            Ss[(wm + gid + 8) * VSTR + cb + 1] = tf32r(s[j][3]);
        }
        sm0 += __shfl_xor_sync(0xffffffffu, sm0, 1);
        sm0 += __shfl_xor_sync(0xffffffffu, sm0, 2);
        sm1 += __shfl_xor_sync(0xffffffffu, sm1, 1);
        sm1 += __shfl_xor_sync(0xffffffffu, sm1, 2);
        if (tig == 0) {
            psum[(wm + gid) * 2 + wq] = sm0;
            psum[(wm + gid + 8) * 2 + wq] = sm1;
        }
        __syncthreads();

        if (tid < 64)
            l_sh[tid] = l_sh[tid] * c_sh[tid] + psum[tid * 2] + psum[tid * 2 + 1];

        // ---- rescale O accumulators, then O += P V ----
        float cr0 = c_sh[wm + gid], cr1 = c_sh[wm + gid + 8];
#pragma unroll
        for (int j = 0; j < 8; j++) {
            o[j][0] *= cr0; o[j][1] *= cr0;
            o[j][2] *= cr1; o[j][3] *= cr1;
        }
#pragma unroll
        for (int k = 0; k < FBN; k += 8) {
            uint32_t a[4];
            a[0] = Ss[(wm + gid) * VSTR + k + tig];
            a[1] = Ss[(wm + gid + 8) * VSTR + k + tig];
            a[2] = Ss[(wm + gid) * VSTR + k + tig + 4];
            a[3] = Ss[(wm + gid + 8) * VSTR + k + tig + 4];
#pragma unroll
            for (int j = 0; j < 8; j++) {
                int n = wq * 64 + j * 8 + gid;   // d index
                uint32_t b0 = Vt[n * VSTR + k + tig];
                uint32_t b1 = Vt[n * VSTR + k + tig + 4];
                mma_tf32(o[j], a, b0, b1);
            }
        }
        __syncthreads();
    }

    // ---- normalize and write ----
    float l0 = l_sh[wm + gid], l1 = l_sh[wm + gid + 8];
    float inv0 = (l0 > 0.f) ? (1.f / l0) : 0.f;
    float inv1 = (l1 > 0.f) ? (1.f / l1) : 0.f;
    float* orow0 = O + (size_t)(b * LSEQ + m0 + wm + gid) * HID + h * HD;
    float* orow1 = O + (size_t)(b * LSEQ + m0 + wm + gid + 8) * HID + h * HD;
#pragma unroll
    for (int j = 0; j < 8; j++) {
        int cb = wq * 64 + j * 8 + 2 * tig;
        *(float2*)(orow0 + cb) = make_float2(o[j][0] * inv0, o[j][1] * inv0);
        *(float2*)(orow1 + cb) = make_float2(o[j][2] * inv1, o[j][3] * inv1);
    }
}

// ---------------- launch ----------------
extern "C" void kernel_launch(void* const* d_in, const int* in_sizes, int n_in,
                              void* d_out, int out_size)
{
    const float* x   = (const float*)d_in[0];
    const int* mask  = (const int*)d_in[1];
    const float* Wq  = (const float*)d_in[2];
    const float* Wk  = (const float*)d_in[3];
    const float* Wv  = (const float*)d_in[4];
    const float* Wo  = (const float*)d_in[5];
    float* out       = (float*)d_out;

    float *Qp, *Kp, *Vp, *Op;
    cudaGetSymbolAddress((void**)&Qp, g_Q);
    cudaGetSymbolAddress((void**)&Kp, g_K);
    cudaGetSymbolAddress((void**)&Vp, g_V);
    cudaGetSymbolAddress((void**)&Op, g_O);

    cudaFuncSetAttribute(gemm_tc, cudaFuncAttributeMaxDynamicSharedMemorySize, GEMM_SMEM);
    cudaFuncSetAttribute(flash_tc, cudaFuncAttributeMaxDynamicSharedMemorySize, FLASH_SMEM);

    gemm_tc<<<dim3(HID / TBN, MTOT / TBM), 256, GEMM_SMEM>>>(x, Wq, Qp, HID);
    gemm_tc<<<dim3(HD / TBN, MTOT / TBM), 256, GEMM_SMEM>>>(x, Wk, Kp, HD);
    gemm_tc<<<dim3(HD / TBN, MTOT / TBM), 256, GEMM_SMEM>>>(x, Wv, Vp, HD);
    flash_tc<<<dim3(LSEQ / FBM, BSZ * NH), 256, FLASH_SMEM>>>(Qp, Kp, Vp, mask, Op);
    gemm_tc<<<dim3(HID / TBN, MTOT / TBM), 256, GEMM_SMEM>>>(Op, Wo, out, HID);
}

// round 9
// speedup vs baseline: 3.4326x; 1.0104x over previous
#include <cuda_runtime.h>
#include <cstdint>
#include <math.h>

// Problem constants
#define BSZ 2
#define LSEQ 2048
#define HID 2048
#define NH 16
#define HD 128
#define MTOT (BSZ * LSEQ)          // 4096
#define SCALE 0.08838834764831845f // 1/sqrt(128)

// ---------------- scratch (no allocations allowed) ----------------
__device__ float g_Q[MTOT * HID];  // 32 MB
__device__ float g_K[MTOT * HD];   // 2 MB
__device__ float g_V[MTOT * HD];   // 2 MB
__device__ float g_O[MTOT * HID];  // 32 MB

// cvt.rna.tf32.f32 writes a .b32 destination -> "=r" constraint.
__device__ __forceinline__ uint32_t tf32r(float x) {
    uint32_t y;
    asm("cvt.rna.tf32.f32 %0, %1;" : "=r"(y) : "f"(x));
    return y;
}

__device__ __forceinline__ void mma_tf32(float* c, const uint32_t* a,
                                         uint32_t b0, uint32_t b1) {
    asm volatile(
        "mma.sync.aligned.m16n8k8.row.col.f32.tf32.tf32.f32 "
        "{%0,%1,%2,%3}, {%4,%5,%6,%7}, {%8,%9}, {%0,%1,%2,%3};\n"
        : "+f"(c[0]), "+f"(c[1]), "+f"(c[2]), "+f"(c[3])
        : "r"(a[0]), "r"(a[1]), "r"(a[2]), "r"(a[3]), "r"(b0), "r"(b1));
}

// ================= mma.sync tf32 GEMM: C[M,N] = A[M,K] @ W[N,K]^T =================
#define TBM 128
#define TBN 128
#define TBK 32
#define GK 2048
#define NCHUNK (GK / TBK)   // 64
#define APAD 36
#define ATILE (TBM * APAD)
#define STAGEF (2 * ATILE)
#define GEMM_SMEM (2 * STAGEF * (int)sizeof(uint32_t))  // 73728 B

__global__ __launch_bounds__(256) void gemm_tc(
    const float* __restrict__ A, const float* __restrict__ W,
    float* __restrict__ C, int ldc)
{
    extern __shared__ uint32_t smw[];
    const int tid = threadIdx.x;
    const int lane = tid & 31;
    const int wid = tid >> 5;
    const int warp_m = (wid & 3) * 32;
    const int warp_n = (wid >> 2) * 64;
    const int gid = lane >> 2;
    const int tig = lane & 3;
    const int bm = blockIdx.y * TBM;
    const int bn = blockIdx.x * TBN;

    const int lrow = tid >> 3;
    const int lc4 = (tid & 7) * 4;

    float acc[2][8][4];
#pragma unroll
    for (int i = 0; i < 2; i++)
#pragma unroll
        for (int j = 0; j < 8; j++)
#pragma unroll
            for (int q = 0; q < 4; q++) acc[i][j][q] = 0.f;

    float4 ra[4], rb[4];

#pragma unroll
    for (int i = 0; i < 4; i++) {
        int row = lrow + i * 32;
        ra[i] = *(const float4*)(A + (size_t)(bm + row) * GK + lc4);
        rb[i] = *(const float4*)(W + (size_t)(bn + row) * GK + lc4);
    }
#pragma unroll
    for (int i = 0; i < 4; i++) {
        int row = lrow + i * 32;
        uint32_t* pa = &smw[row * APAD + lc4];
        uint32_t* pb = &smw[ATILE + row * APAD + lc4];
        pa[0] = tf32r(ra[i].x); pa[1] = tf32r(ra[i].y);
        pa[2] = tf32r(ra[i].z); pa[3] = tf32r(ra[i].w);
        pb[0] = tf32r(rb[i].x); pb[1] = tf32r(rb[i].y);
        pb[2] = tf32r(rb[i].z); pb[3] = tf32r(rb[i].w);
    }
    __syncthreads();

#pragma unroll 1
    for (int c = 0; c < NCHUNK; c++) {
        const int s = c & 1;
        const bool more = (c + 1 < NCHUNK);
        if (more) {
            const int k0 = (c + 1) * TBK;
#pragma unroll
            for (int i = 0; i < 4; i++) {
                int row = lrow + i * 32;
                ra[i] = *(const float4*)(A + (size_t)(bm + row) * GK + k0 + lc4);
                rb[i] = *(const float4*)(W + (size_t)(bn + row) * GK + k0 + lc4);
            }
        }

        const uint32_t* As_ = &smw[s * STAGEF];
        const uint32_t* Ws_ = &smw[s * STAGEF + ATILE];
#pragma unroll
        for (int ks = 0; ks < 4; ks++) {
            const int k = ks * 8;
            uint32_t af[2][4];
#pragma unroll
            for (int i = 0; i < 2; i++) {
                int r0 = warp_m + i * 16 + gid;
                af[i][0] = As_[r0 * APAD + k + tig];
                af[i][1] = As_[(r0 + 8) * APAD + k + tig];
                af[i][2] = As_[r0 * APAD + k + tig + 4];
                af[i][3] = As_[(r0 + 8) * APAD + k + tig + 4];
            }
#pragma unroll
            for (int j = 0; j < 8; j++) {
                int cn = warp_n + j * 8 + gid;
                uint32_t b0 = Ws_[cn * APAD + k + tig];
                uint32_t b1 = Ws_[cn * APAD + k + tig + 4];
                mma_tf32(acc[0][j], af[0], b0, b1);
                mma_tf32(acc[1][j], af[1], b0, b1);
            }
        }

        if (more) {
            uint32_t* Ad = &smw[(s ^ 1) * STAGEF];
            uint32_t* Bd = &smw[(s ^ 1) * STAGEF + ATILE];
#pragma unroll
            for (int i = 0; i < 4; i++) {
                int row = lrow + i * 32;
                uint32_t* pa = &Ad[row * APAD + lc4];
                uint32_t* pb = &Bd[row * APAD + lc4];
                pa[0] = tf32r(ra[i].x); pa[1] = tf32r(ra[i].y);
                pa[2] = tf32r(ra[i].z); pa[3] = tf32r(ra[i].w);
                pb[0] = tf32r(rb[i].x); pb[1] = tf32r(rb[i].y);
                pb[2] = tf32r(rb[i].z); pb[3] = tf32r(rb[i].w);
            }
        }
        __syncthreads();
    }

#pragma unroll
    for (int i = 0; i < 2; i++) {
        int r0 = bm + warp_m + i * 16 + gid;
#pragma unroll
        for (int j = 0; j < 8; j++) {
            int cn = bn + warp_n + j * 8 + 2 * tig;
            *(float2*)(C + (size_t)r0 * ldc + cn) =
                make_float2(acc[i][j][0], acc[i][j][1]);
            *(float2*)(C + (size_t)(r0 + 8) * ldc + cn) =
                make_float2(acc[i][j][2], acc[i][j][3]);
        }
    }
}

// ============== Flash attention v2 (tf32 mma, warp-owns-rows, causal, MQA) ==============
// CTA: 128 q-rows x full head (d=128). 8 warps; warp w owns rows w*16..w*16+15.
// Warp S tile: m16 x n64 -> softmax fully warp-local (quad shuffles, register stats).
// P transposed to A-fragments via intra-quad shuffles (no smem round-trip).
// K/V smem double-buffered; register-staged global loads; ONE syncthreads per tile.
#define FBM 128
#define FBN 64
#define QSTR 132   // stride mod 32 = 4 -> bank = 4*gid + tig (conflict-free)
#define VSTR 68
#define KTILE (64 * QSTR)
#define VTILE (128 * VSTR)
#define FL_QS 0
#define FL_KS (FL_QS + FBM * QSTR)       // Qs: 16896 words
#define FL_VT (FL_KS + 2 * KTILE)        // Ks: 2 x 8448
#define FL_MK (FL_VT + 2 * VTILE)        // Vt: 2 x 8704
#define FLASH_SMEM ((FL_MK + 2 * 64) * (int)sizeof(uint32_t))  // 205,824 B

__global__ __launch_bounds__(256) void flash_tc(
    const float* __restrict__ Q, const float* __restrict__ K,
    const float* __restrict__ V, const int* __restrict__ mask,
    float* __restrict__ O)
{
    extern __shared__ uint32_t fsw[];
    uint32_t* Qs = fsw + FL_QS;
    uint32_t* Ksb = fsw + FL_KS;
    uint32_t* Vtb = fsw + FL_VT;
    int* mkb = (int*)(fsw + FL_MK);

    const int m0 = (gridDim.x - 1 - blockIdx.x) * FBM;  // heavy tiles first
    const int bh = blockIdx.y;
    const int b = bh / NH;
    const int h = bh % NH;
    const int tid = threadIdx.x;
    const int lane = tid & 31;
    const int wid = tid >> 5;
    const int gid = lane >> 2;
    const int tig = lane & 3;
    const int wm = wid * 16;

    // ---- Q tile (128 x 128) -> tf32 smem ----
    for (int f = tid; f < FBM * 32; f += 256) {
        int row = f >> 5, c4 = (f & 31) * 4;
        float4 v = *(const float4*)(Q + (size_t)(b * LSEQ + m0 + row) * HID + h * HD + c4);
        uint4 u = make_uint4(tf32r(v.x), tf32r(v.y), tf32r(v.z), tf32r(v.w));
        *(uint4*)&Qs[row * QSTR + c4] = u;
    }
    // ---- prologue: KV tile 0 into buffer 0 ----
    for (int f = tid; f < 64 * 32; f += 256) {
        int row = f >> 5, c4 = (f & 31) * 4;
        float4 v = *(const float4*)(K + (size_t)(b * LSEQ + row) * HD + c4);
        uint4 u = make_uint4(tf32r(v.x), tf32r(v.y), tf32r(v.z), tf32r(v.w));
        *(uint4*)&Ksb[row * QSTR + c4] = u;
    }
    for (int f = tid; f < 64 * 32; f += 256) {
        int row = f & 63, c4 = (f >> 6) * 4;
        float4 v = *(const float4*)(V + (size_t)(b * LSEQ + row) * HD + c4);
        Vtb[(c4 + 0) * VSTR + row] = tf32r(v.x);
        Vtb[(c4 + 1) * VSTR + row] = tf32r(v.y);
        Vtb[(c4 + 2) * VSTR + row] = tf32r(v.z);
        Vtb[(c4 + 3) * VSTR + row] = tf32r(v.w);
    }
    if (tid < 64) mkb[tid] = mask[b * LSEQ + tid];
    __syncthreads();

    float o[16][4];
#pragma unroll
    for (int dj = 0; dj < 16; dj++)
#pragma unroll
        for (int c = 0; c < 4; c++) o[dj][c] = 0.f;
    float m_a = -1e30f, m_b = -1e30f, l_a = 0.f, l_b = 0.f;

    const int rA = m0 + wm + gid;
    const int rB = rA + 8;
    const int srcA = (lane & ~3) | (tig >> 1);
    const int srcB = srcA + 2;
    const int ntiles = m0 / FBN + FBM / FBN;  // m0/64 + 2

#pragma unroll 1
    for (int t = 0; t < ntiles; t++) {
        const int buf = t & 1;
        const uint32_t* Ks = Ksb + buf * KTILE;
        const uint32_t* Vt = Vtb + buf * VTILE;
        const int* mk = mkb + buf * 64;
        const int n0 = t * FBN;
        const bool more = (t + 1 < ntiles);

        // ---- stage next KV tile in registers (latency hidden by compute) ----
        float4 ka[8], va[8];
        int mreg = 1;
        if (more) {
            const int nn = n0 + FBN;
#pragma unroll
            for (int i = 0; i < 8; i++) {
                int f = tid + i * 256;
                int row = f >> 5, c4 = (f & 31) * 4;
                ka[i] = *(const float4*)(K + (size_t)(b * LSEQ + nn + row) * HD + c4);
            }
#pragma unroll
            for (int i = 0; i < 8; i++) {
                int f = tid + i * 256;
                int row = f & 63, c4 = (f >> 6) * 4;
                va[i] = *(const float4*)(V + (size_t)(b * LSEQ + nn + row) * HD + c4);
            }
            if (tid < 64) mreg = mask[b * LSEQ + nn + tid];
        }

        if (n0 <= m0 + wm + 15) {   // per-warp causal skip
            // ---- S = Q K^T : warp m16 x n64 ----
            float s[8][4];
#pragma unroll
            for (int j = 0; j < 8; j++)
#pragma unroll
                for (int c = 0; c < 4; c++) s[j][c] = 0.f;
#pragma unroll
            for (int k8 = 0; k8 < 16; k8++) {
                const int k = k8 * 8;
                uint32_t a[4];
                a[0] = Qs[(wm + gid) * QSTR + k + tig];
                a[1] = Qs[(wm + gid + 8) * QSTR + k + tig];
                a[2] = Qs[(wm + gid) * QSTR + k + tig + 4];
                a[3] = Qs[(wm + gid + 8) * QSTR + k + tig + 4];
#pragma unroll
                for (int j = 0; j < 8; j++) {
                    uint32_t b0 = Ks[(j * 8 + gid) * QSTR + k + tig];
                    uint32_t b1 = Ks[(j * 8 + gid) * QSTR + k + tig + 4];
                    mma_tf32(s[j], a, b0, b1);
                }
            }

            // ---- scale + causal + pad mask; warp-local row max ----
            float mxA = -1e30f, mxB = -1e30f;
#pragma unroll
            for (int j = 0; j < 8; j++) {
#pragma unroll
                for (int c = 0; c < 4; c++) {
                    int lcol = j * 8 + 2 * tig + (c & 1);
                    int col = n0 + lcol;
                    int r = (c < 2) ? rA : rB;
                    float v = s[j][c] * SCALE;
                    if (col > r || mk[lcol] == 0) v = -1e30f;
                    s[j][c] = v;
                    if (c < 2) mxA = fmaxf(mxA, v); else mxB = fmaxf(mxB, v);
                }
            }
            mxA = fmaxf(mxA, __shfl_xor_sync(0xffffffffu, mxA, 1));
            mxA = fmaxf(mxA, __shfl_xor_sync(0xffffffffu, mxA, 2));
            mxB = fmaxf(mxB, __shfl_xor_sync(0xffffffffu, mxB, 1));
            mxB = fmaxf(mxB, __shfl_xor_sync(0xffffffffu, mxB, 2));
            const float mnA = fmaxf(m_a, mxA), mnB = fmaxf(m_b, mxB);
            const float crA = __expf(m_a - mnA), crB = __expf(m_b - mnB);
            m_a = mnA; m_b = mnB;

            // ---- exp + row sums ----
            float smA = 0.f, smB = 0.f;
#pragma unroll
            for (int j = 0; j < 8; j++) {
#pragma unroll
                for (int c = 0; c < 4; c++) {
                    float p = __expf(s[j][c] - ((c < 2) ? mnA : mnB));
                    s[j][c] = p;
                    if (c < 2) smA += p; else smB += p;
                }
            }
            smA += __shfl_xor_sync(0xffffffffu, smA, 1);
            smA += __shfl_xor_sync(0xffffffffu, smA, 2);
            smB += __shfl_xor_sync(0xffffffffu, smB, 1);
            smB += __shfl_xor_sync(0xffffffffu, smB, 2);
            l_a = l_a * crA + smA;
            l_b = l_b * crB + smB;

            // ---- rescale O, then O += P V (P via intra-quad shuffle transpose) ----
#pragma unroll
            for (int dj = 0; dj < 16; dj++) {
                o[dj][0] *= crA; o[dj][1] *= crA;
                o[dj][2] *= crB; o[dj][3] *= crB;
            }
#pragma unroll
            for (int j = 0; j < 8; j++) {   // j = k8-group of PV
                float v0 = __shfl_sync(0xffffffffu, s[j][0], srcA);
                float v1 = __shfl_sync(0xffffffffu, s[j][1], srcA);
                float v2 = __shfl_sync(0xffffffffu, s[j][2], srcA);
                float v3 = __shfl_sync(0xffffffffu, s[j][3], srcA);
                float w0 = __shfl_sync(0xffffffffu, s[j][0], srcB);
                float w1 = __shfl_sync(0xffffffffu, s[j][1], srcB);
                float w2 = __shfl_sync(0xffffffffu, s[j][2], srcB);
                float w3 = __shfl_sync(0xffffffffu, s[j][3], srcB);
                uint32_t a[4];
                a[0] = tf32r((tig & 1) ? v1 : v0);   // row gid,   col j*8+tig
                a[1] = tf32r((tig & 1) ? v3 : v2);   // row gid+8, col j*8+tig
                a[2] = tf32r((tig & 1) ? w1 : w0);   // row gid,   col j*8+tig+4
                a[3] = tf32r((tig & 1) ? w3 : w2);   // row gid+8, col j*8+tig+4
                const int k = j * 8;
#pragma unroll
                for (int dj = 0; dj < 16; dj++) {
                    uint32_t b0 = Vt[(dj * 8 + gid) * VSTR + k + tig];
                    uint32_t b1 = Vt[(dj * 8 + gid) * VSTR + k + tig + 4];
                    mma_tf32(o[dj], a, b0, b1);
                }
            }
        }

        // ---- commit staged tile into other buffer ----
        if (more) {
            uint32_t* Kd = Ksb + (buf ^ 1) * KTILE;
            uint32_t* Vd = Vtb + (buf ^ 1) * VTILE;
#pragma unroll
            for (int i = 0; i < 8; i++) {
                int f = tid + i * 256;
                int row = f >> 5, c4 = (f & 31) * 4;
                uint4 u = make_uint4(tf32r(ka[i].x), tf32r(ka[i].y),
                                     tf32r(ka[i].z), tf32r(ka[i].w));
                *(uint4*)&Kd[row * QSTR + c4] = u;
            }
#pragma unroll
            for (int i = 0; i < 8; i++) {
                int f = tid + i * 256;
                int row = f & 63, c4 = (f >> 6) * 4;
                Vd[(c4 + 0) * VSTR + row] = tf32r(va[i].x);
                Vd[(c4 + 1) * VSTR + row] = tf32r(va[i].y);
                Vd[(c4 + 2) * VSTR + row] = tf32r(va[i].z);
                Vd[(c4 + 3) * VSTR + row] = tf32r(va[i].w);
            }
            if (tid < 64) mkb[(buf ^ 1) * 64 + tid] = mreg;
        }
        __syncthreads();
    }

    // ---- normalize + write ----
    const float invA = (l_a > 0.f) ? (1.f / l_a) : 0.f;
    const float invB = (l_b > 0.f) ? (1.f / l_b) : 0.f;
    float* rowA = O + (size_t)(b * LSEQ + m0 + wm + gid) * HID + h * HD;
    float* rowB = rowA + (size_t)8 * HID;
#pragma unroll
    for (int dj = 0; dj < 16; dj++) {
        int cb = dj * 8 + 2 * tig;
        *(float2*)(rowA + cb) = make_float2(o[dj][0] * invA, o[dj][1] * invA);
        *(float2*)(rowB + cb) = make_float2(o[dj][2] * invB, o[dj][3] * invB);
    }
}

// ---------------- launch ----------------
extern "C" void kernel_launch(void* const* d_in, const int* in_sizes, int n_in,
                              void* d_out, int out_size)
{
    const float* x   = (const float*)d_in[0];
    const int* mask  = (const int*)d_in[1];
    const float* Wq  = (const float*)d_in[2];
    const float* Wk  = (const float*)d_in[3];
    const float* Wv  = (const float*)d_in[4];
    const float* Wo  = (const float*)d_in[5];
    float* out       = (float*)d_out;

    float *Qp, *Kp, *Vp, *Op;
    cudaGetSymbolAddress((void**)&Qp, g_Q);
    cudaGetSymbolAddress((void**)&Kp, g_K);
    cudaGetSymbolAddress((void**)&Vp, g_V);
    cudaGetSymbolAddress((void**)&Op, g_O);

    cudaFuncSetAttribute(gemm_tc, cudaFuncAttributeMaxDynamicSharedMemorySize, GEMM_SMEM);
    cudaFuncSetAttribute(flash_tc, cudaFuncAttributeMaxDynamicSharedMemorySize, FLASH_SMEM);

    gemm_tc<<<dim3(HID / TBN, MTOT / TBM), 256, GEMM_SMEM>>>(x, Wq, Qp, HID);
    gemm_tc<<<dim3(HD / TBN, MTOT / TBM), 256, GEMM_SMEM>>>(x, Wk, Kp, HD);
    gemm_tc<<<dim3(HD / TBN, MTOT / TBM), 256, GEMM_SMEM>>>(x, Wv, Vp, HD);
    flash_tc<<<dim3(LSEQ / FBM, BSZ * NH), 256, FLASH_SMEM>>>(Qp, Kp, Vp, mask, Op);
    gemm_tc<<<dim3(HID / TBN, MTOT / TBM), 256, GEMM_SMEM>>>(Op, Wo, out, HID);
}